// round 1
// baseline (speedup 1.0000x reference)
#include <cuda_runtime.h>
#include <cstdint>

// Problem constants
#define BN 32
#define LN 32768
#define MN 32
#define DN 128
#define KN 16
#define SN 8
#define PN 4095   // (L - K)/STRIDE + 1

// Pre-packed weights: for k-iter t (16), kf f (4), n=d (128), q (4):
// float2 { W'[n][t*32 + f*8 + q], W'[n][t*32 + f*8 + q + 4] }  (tf32 bit patterns)
// where W'[n][r] = conv_w[n*512 + (r%32)*16 + (r/32)]  (r = k*32 + m)
__device__ float2 g_Wp[16 * 4 * 128 * 4];   // 256 KB scratch (device global, no alloc)

__device__ __forceinline__ uint32_t f2tf32(float v) {
    uint32_t u;
    asm("cvt.rna.tf32.f32 %0, %1;" : "=r"(u) : "f"(v));
    return u;
}

__global__ void pack_w_kernel(const float* __restrict__ w) {
    int idx = blockIdx.x * blockDim.x + threadIdx.x;   // 0..32767
    int q = idx & 3;
    int n = (idx >> 2) & 127;
    int f = (idx >> 9) & 3;
    int t = idx >> 11;
    int m0 = f * 8 + q;
    float v0 = w[n * 512 + m0 * 16 + t];
    float v1 = w[n * 512 + (m0 + 4) * 16 + t];
    float2 o;
    o.x = __uint_as_float(f2tf32(v0));
    o.y = __uint_as_float(f2tf32(v1));
    g_Wp[idx] = o;
}

__device__ __forceinline__ void mma_tf32(float c[4], const uint32_t a[4],
                                         uint32_t b0, uint32_t b1) {
    asm volatile(
        "mma.sync.aligned.m16n8k8.row.col.f32.tf32.tf32.f32 "
        "{%0,%1,%2,%3}, {%4,%5,%6,%7}, {%8,%9}, {%0,%1,%2,%3};\n"
        : "+f"(c[0]), "+f"(c[1]), "+f"(c[2]), "+f"(c[3])
        : "r"(a[0]), "r"(a[1]), "r"(a[2]), "r"(a[3]), "r"(b0), "r"(b1));
}

// CTA: 128 patches x 128 D.  256 threads = 8 warps, warp tile 32(m) x 64(n).
// K = 512 in 16 chunks of 32.
__global__ __launch_bounds__(256) void patch_encoder_kernel(
    const float* __restrict__ x,     // (B, L, M)
    const float* __restrict__ ts,    // (B, L)
    const float* __restrict__ bias,  // (D,)
    float* __restrict__ out)         // (B, P, D)
{
    __shared__ uint32_t Ash[128 * 36];   // 128 rows x 32 tf32, pad to 36
    __shared__ float4   Bsh[1024];       // 2048 float2 = one k-chunk of packed W
    __shared__ float    meds[128];
    __shared__ float    sbias[128];
    __shared__ float    sdiv[64];

    const int tid  = threadIdx.x;
    const int b    = blockIdx.y;
    const int p0   = blockIdx.x * 128;
    const int wid  = tid >> 5;
    const int lane = tid & 31;
    const int wm   = wid & 3;     // 0..3 -> m offset wm*32
    const int wn   = wid >> 2;    // 0..1 -> n offset wn*64
    const int g    = lane >> 2;   // groupID
    const int q    = lane & 3;    // threadID in group

    if (tid < 128) {
        int p = p0 + tid;
        meds[tid]  = (p < PN) ? ts[(size_t)b * LN + p * SN + 7] : 0.0f;
        sbias[tid] = bias[tid];
    }
    if (tid < 64) {
        // div_term[i] = exp(2i * (-ln(10000)/128))
        sdiv[tid] = expf((float)(2 * tid) * -0.07195578800731849f);
    }

    float acc[2][8][4];
#pragma unroll
    for (int mf = 0; mf < 2; mf++)
#pragma unroll
        for (int nf = 0; nf < 8; nf++)
#pragma unroll
            for (int i = 0; i < 4; i++) acc[mf][nf][i] = 0.0f;

    const float* xbase = x + ((size_t)b * LN + (size_t)p0 * SN) * MN;

    for (int t = 0; t < 16; t++) {
        // ---- load A tile: 128 patches x 32 floats (contiguous per patch) ----
#pragma unroll
        for (int it = 0; it < 4; it++) {
            int lin = it * 256 + tid;        // 0..1023 float4 slots
            int tm  = lin >> 3;              // patch row in tile
            int j   = lin & 7;               // float4 index within 32 floats
            float4 v = make_float4(0.f, 0.f, 0.f, 0.f);
            if (p0 + tm < PN)
                v = *(const float4*)(xbase + tm * 256 + t * 32 + j * 4);
            uint4 u;
            u.x = f2tf32(v.x); u.y = f2tf32(v.y);
            u.z = f2tf32(v.z); u.w = f2tf32(v.w);
            *(uint4*)(Ash + tm * 36 + j * 4) = u;
        }
        // ---- load B tile: 16 KB contiguous from packed weights ----
        const float4* wp4 = (const float4*)g_Wp + t * 1024;
#pragma unroll
        for (int it = 0; it < 4; it++)
            Bsh[it * 256 + tid] = wp4[it * 256 + tid];

        __syncthreads();

        // ---- compute: 4 kf x (2 mf x 8 nf) mma.m16n8k8 ----
#pragma unroll
        for (int kf = 0; kf < 4; kf++) {
            uint32_t a[2][4];
#pragma unroll
            for (int mf = 0; mf < 2; mf++) {
                int row = wm * 32 + mf * 16 + g;
                a[mf][0] = Ash[row * 36 + kf * 8 + q];
                a[mf][1] = Ash[(row + 8) * 36 + kf * 8 + q];
                a[mf][2] = Ash[row * 36 + kf * 8 + q + 4];
                a[mf][3] = Ash[(row + 8) * 36 + kf * 8 + q + 4];
            }
            const float2* B2 = (const float2*)Bsh;
#pragma unroll
            for (int nf = 0; nf < 8; nf++) {
                int n = wn * 64 + nf * 8 + g;
                float2 bb = B2[kf * 512 + n * 4 + q];
                uint32_t b0 = __float_as_uint(bb.x);
                uint32_t b1 = __float_as_uint(bb.y);
                mma_tf32(acc[0][nf], a[0], b0, b1);
                mma_tf32(acc[1][nf], a[1], b0, b1);
            }
        }
        __syncthreads();
    }

    // ---- epilogue: + bias + positional encoding, write out ----
#pragma unroll
    for (int mf = 0; mf < 2; mf++) {
        int r0 = wm * 32 + mf * 16 + g;
        int r1 = r0 + 8;
        float med0 = meds[r0];
        float med1 = meds[r1];
        bool ok0 = (p0 + r0) < PN;
        bool ok1 = (p0 + r1) < PN;
        size_t base0 = ((size_t)b * PN + (size_t)(p0 + r0)) * DN;
        size_t base1 = ((size_t)b * PN + (size_t)(p0 + r1)) * DN;
#pragma unroll
        for (int nf = 0; nf < 8; nf++) {
            int col = wn * 64 + nf * 8 + 2 * q;   // even
            float dv = sdiv[col >> 1];
            float bs0 = sbias[col];
            float bs1 = sbias[col + 1];
            float s, c;
            if (ok0) {
                sincosf(med0 * dv, &s, &c);
                float2 v;
                v.x = acc[mf][nf][0] + bs0 + s;
                v.y = acc[mf][nf][1] + bs1 + c;
                *(float2*)(out + base0 + col) = v;
            }
            if (ok1) {
                sincosf(med1 * dv, &s, &c);
                float2 v;
                v.x = acc[mf][nf][2] + bs0 + s;
                v.y = acc[mf][nf][3] + bs1 + c;
                *(float2*)(out + base1 + col) = v;
            }
        }
    }
}

extern "C" void kernel_launch(void* const* d_in, const int* in_sizes, int n_in,
                              void* d_out, int out_size) {
    const float* x    = (const float*)d_in[0];
    const float* ts   = (const float*)d_in[1];
    const float* w    = (const float*)d_in[2];
    const float* bias = (const float*)d_in[3];
    float* out = (float*)d_out;

    pack_w_kernel<<<128, 256>>>(w);

    dim3 grid((PN + 127) / 128, BN);   // 32 x 32 CTAs
    patch_encoder_kernel<<<grid, 256>>>(x, ts, bias, out);
}

// round 4
// speedup vs baseline: 2.2785x; 2.2785x over previous
#include <cuda_runtime.h>
#include <cuda_fp16.h>
#include <cstdint>

// Problem constants
#define BN 32
#define LN 32768
#define DN 128
#define PN 4095   // (L-K)/STRIDE + 1

// ---------------------------------------------------------------------------
// Pre-packed B (fp16): [16 chunks][128 n][32 k] halfs, contiguous (64B/row).
// chunk t, row n (=d), col kk (=m): element = conv_w[n*512 + kk*16 + t]
// ---------------------------------------------------------------------------
__device__ __half g_Bh[16 * 128 * 32];   // 128 KB

__global__ void pack_w_kernel(const float* __restrict__ w) {
    int idx = blockIdx.x * blockDim.x + threadIdx.x;  // 0..65535
    int t  = idx >> 12;
    int n  = (idx >> 5) & 127;
    int kk = idx & 31;
    g_Bh[idx] = __float2half_rn(w[n * 512 + kk * 16 + t]);
}

__device__ __forceinline__ uint32_t pack_h2(float x, float y) {
    uint32_t r;
    asm("{ .reg .f16 lo, hi;\n\t"
        "cvt.rn.f16.f32 lo, %1;\n\t"
        "cvt.rn.f16.f32 hi, %2;\n\t"
        "mov.b32 %0, {lo, hi}; }"
        : "=r"(r) : "f"(x), "f"(y));
    return r;
}

__device__ __forceinline__ void mma_f16(float c[4], const uint32_t a[4],
                                        uint32_t b0, uint32_t b1) {
    asm volatile(
        "mma.sync.aligned.m16n8k16.row.col.f32.f16.f16.f32 "
        "{%0,%1,%2,%3}, {%4,%5,%6,%7}, {%8,%9}, {%0,%1,%2,%3};\n"
        : "+f"(c[0]), "+f"(c[1]), "+f"(c[2]), "+f"(c[3])
        : "r"(a[0]), "r"(a[1]), "r"(a[2]), "r"(a[3]), "r"(b0), "r"(b1));
}

__device__ __forceinline__ uint32_t smem_u32(const void* p) {
    uint32_t a;
    asm("{ .reg .u64 t; cvta.to.shared.u64 t, %1; cvt.u32.u64 %0, t; }"
        : "=r"(a) : "l"(p));
    return a;
}

// SMEM tiles: rows padded to 40 halfs (80 B) -> bank-conflict-free fragment LDS
#define ROWB 80
#define TILEB (128 * ROWB)   // 10240 B per stage

// CTA: 128 patches x 128 D, 256 threads = 8 warps, warp tile 32(m) x 64(n).
// K = 512 in 16 chunks of 32, double-buffered pipeline.
__global__ __launch_bounds__(256, 2) void patch_encoder_kernel(
    const float* __restrict__ x,     // (B, L, M)
    const float* __restrict__ ts,    // (B, L)
    const float* __restrict__ bias,  // (D,)
    float* __restrict__ out)         // (B, P, D)
{
    __shared__ __align__(16) unsigned char Abuf[2][TILEB];
    __shared__ __align__(16) unsigned char Bbuf[2][TILEB];
    __shared__ float meds[128];
    __shared__ float sbias[128];
    __shared__ float sdiv[64];

    const int tid  = threadIdx.x;
    const int b    = blockIdx.y;
    const int p0   = blockIdx.x * 128;
    const int wid  = tid >> 5;
    const int lane = tid & 31;
    const int wm   = wid & 3;     // m offset wm*32
    const int wn   = wid >> 2;    // n offset wn*64
    const int g    = lane >> 2;
    const int q    = lane & 3;

    if (tid < 128) {
        int p = p0 + tid;
        meds[tid]  = (p < PN) ? ts[(size_t)b * LN + p * 8 + 7] : 0.0f;
        sbias[tid] = bias[tid];
    }
    if (tid < 64)
        sdiv[tid] = expf((float)(2 * tid) * -0.07195578800731849f);

    float acc[2][8][4];
#pragma unroll
    for (int mf = 0; mf < 2; mf++)
#pragma unroll
        for (int nf = 0; nf < 8; nf++)
#pragma unroll
            for (int i = 0; i < 4; i++) acc[mf][nf][i] = 0.0f;

    const float* xbase = x + ((size_t)b * LN + (size_t)p0 * 8) * 32;
    const char*  gB    = (const char*)g_Bh;

    // per-thread tile-load coords: 512 16B-slots, 2 per thread
    // slot lin: r = lin>>2 (patch row), j = lin&3 (16B chunk within 64B row)
    const int r0 = tid >> 2;          // slot set 0: lin = tid
    const int j0 = tid & 3;
    const int r1 = (256 + tid) >> 2;  // slot set 1: lin = 256 + tid
    const int j1 = tid & 3;

    float4 va[2][2];   // prefetch registers: 2 slots x 2 float4

    // ---- prefetch helpers (macros keep regs in scope) ----
#define LOAD_A(t_)                                                            \
    do {                                                                      \
        va[0][0] = make_float4(0.f, 0.f, 0.f, 0.f);                           \
        va[0][1] = va[0][0]; va[1][0] = va[0][0]; va[1][1] = va[0][0];        \
        if (p0 + r0 < PN) {                                                   \
            const float* s = xbase + ((size_t)r0 * 8 + (t_)) * 32 + j0 * 8;   \
            va[0][0] = *(const float4*)s;                                     \
            va[0][1] = *(const float4*)(s + 4);                               \
        }                                                                     \
        if (p0 + r1 < PN) {                                                   \
            const float* s = xbase + ((size_t)r1 * 8 + (t_)) * 32 + j1 * 8;   \
            va[1][0] = *(const float4*)s;                                     \
            va[1][1] = *(const float4*)(s + 4);                               \
        }                                                                     \
    } while (0)

#define CPASYNC_B(t_, buf_)                                                   \
    do {                                                                      \
        uint32_t d0 = smem_u32(&Bbuf[buf_][r0 * ROWB + j0 * 16]);             \
        uint32_t d1 = smem_u32(&Bbuf[buf_][r1 * ROWB + j1 * 16]);             \
        const char* s0 = gB + (t_) * 8192 + r0 * 64 + j0 * 16;                \
        const char* s1 = gB + (t_) * 8192 + r1 * 64 + j1 * 16;                \
        asm volatile("cp.async.ca.shared.global [%0], [%1], 16;" :: "r"(d0), "l"(s0)); \
        asm volatile("cp.async.ca.shared.global [%0], [%1], 16;" :: "r"(d1), "l"(s1)); \
        asm volatile("cp.async.commit_group;");                               \
    } while (0)

#define STS_A(buf_)                                                           \
    do {                                                                      \
        uint32_t d0 = smem_u32(&Abuf[buf_][r0 * ROWB + j0 * 16]);             \
        uint32_t d1 = smem_u32(&Abuf[buf_][r1 * ROWB + j1 * 16]);             \
        uint32_t h0 = pack_h2(va[0][0].x, va[0][0].y);                        \
        uint32_t h1 = pack_h2(va[0][0].z, va[0][0].w);                        \
        uint32_t h2 = pack_h2(va[0][1].x, va[0][1].y);                        \
        uint32_t h3 = pack_h2(va[0][1].z, va[0][1].w);                        \
        asm volatile("st.shared.v4.b32 [%0], {%1,%2,%3,%4};"                  \
                     :: "r"(d0), "r"(h0), "r"(h1), "r"(h2), "r"(h3));         \
        h0 = pack_h2(va[1][0].x, va[1][0].y);                                 \
        h1 = pack_h2(va[1][0].z, va[1][0].w);                                 \
        h2 = pack_h2(va[1][1].x, va[1][1].y);                                 \
        h3 = pack_h2(va[1][1].z, va[1][1].w);                                 \
        asm volatile("st.shared.v4.b32 [%0], {%1,%2,%3,%4};"                  \
                     :: "r"(d1), "r"(h0), "r"(h1), "r"(h2), "r"(h3));         \
    } while (0)

    // ---- prologue: tile 0 ----
    LOAD_A(0);
    CPASYNC_B(0, 0);
    STS_A(0);
    asm volatile("cp.async.wait_group 0;" ::: "memory");
    __syncthreads();

    // fragment base addresses (bank-conflict-free: row*80 -> 8 distinct banks)
    const uint32_t aRowBase0 = smem_u32(&Abuf[0][0]) + (wm * 32 + g) * ROWB + q * 4;
    const uint32_t bRowBase0 = smem_u32(&Bbuf[0][0]) + (wn * 64 + g) * ROWB + q * 4;

    for (int t = 0; t < 16; t++) {
        const int cur = t & 1;
        const int nxt = cur ^ 1;

        if (t < 15) {
            LOAD_A(t + 1);
            CPASYNC_B(t + 1, nxt);
        }

        // ---- compute: 2 k16-steps x (2 mf x 8 nf) mmas ----
        const uint32_t aB = aRowBase0 + cur * TILEB;
        const uint32_t bB = bRowBase0 + cur * TILEB;
#pragma unroll
        for (int ks = 0; ks < 2; ks++) {
            uint32_t a[2][4];
#pragma unroll
            for (int mf = 0; mf < 2; mf++) {
                uint32_t ad = aB + mf * (16 * ROWB) + ks * 32;
                asm volatile("ld.shared.b32 %0, [%1];"       : "=r"(a[mf][0]) : "r"(ad));
                asm volatile("ld.shared.b32 %0, [%1+640];"   : "=r"(a[mf][1]) : "r"(ad));
                asm volatile("ld.shared.b32 %0, [%1+16];"    : "=r"(a[mf][2]) : "r"(ad));
                asm volatile("ld.shared.b32 %0, [%1+656];"   : "=r"(a[mf][3]) : "r"(ad));
            }
#pragma unroll
            for (int nf = 0; nf < 8; nf++) {
                uint32_t bd = bB + nf * (8 * ROWB) + ks * 32;
                uint32_t b0, b1;
                asm volatile("ld.shared.b32 %0, [%1];"    : "=r"(b0) : "r"(bd));
                asm volatile("ld.shared.b32 %0, [%1+16];" : "=r"(b1) : "r"(bd));
                mma_f16(acc[0][nf], a[0], b0, b1);
                mma_f16(acc[1][nf], a[1], b0, b1);
            }
        }

        if (t < 15) {
            STS_A(nxt);
            asm volatile("cp.async.wait_group 0;" ::: "memory");
        }
        __syncthreads();
    }

    // ---- epilogue: + bias + positional encoding, write out ----
#pragma unroll
    for (int mf = 0; mf < 2; mf++) {
        int rr0 = wm * 32 + mf * 16 + g;
        int rr1 = rr0 + 8;
        float med0 = meds[rr0];
        float med1 = meds[rr1];
        bool ok0 = (p0 + rr0) < PN;
        bool ok1 = (p0 + rr1) < PN;
        size_t base0 = ((size_t)b * PN + (size_t)(p0 + rr0)) * DN;
        size_t base1 = ((size_t)b * PN + (size_t)(p0 + rr1)) * DN;
#pragma unroll
        for (int nf = 0; nf < 8; nf++) {
            int col = wn * 64 + nf * 8 + 2 * q;   // even
            float dv = sdiv[col >> 1];
            float bs0 = sbias[col];
            float bs1 = sbias[col + 1];
            float s, c;
            if (ok0) {
                sincosf(med0 * dv, &s, &c);
                float2 v;
                v.x = (mf ? acc[1][nf][0] : acc[0][nf][0]) + bs0 + s;
                v.y = (mf ? acc[1][nf][1] : acc[0][nf][1]) + bs1 + c;
                *(float2*)(out + base0 + col) = v;
            }
            if (ok1) {
                sincosf(med1 * dv, &s, &c);
                float2 v;
                v.x = (mf ? acc[1][nf][2] : acc[0][nf][2]) + bs0 + s;
                v.y = (mf ? acc[1][nf][3] : acc[0][nf][3]) + bs1 + c;
                *(float2*)(out + base1 + col) = v;
            }
        }
    }
}

extern "C" void kernel_launch(void* const* d_in, const int* in_sizes, int n_in,
                              void* d_out, int out_size) {
    const float* x    = (const float*)d_in[0];
    const float* ts   = (const float*)d_in[1];
    const float* w    = (const float*)d_in[2];
    const float* bias = (const float*)d_in[3];
    float* out = (float*)d_out;

    pack_w_kernel<<<256, 256>>>(w);

    dim3 grid(32, BN);   // 32 patch-tiles x 32 batches
    patch_encoder_kernel<<<grid, 256>>>(x, ts, bias, out);
}